// round 1
// baseline (speedup 1.0000x reference)
#include <cuda_runtime.h>
#include <cstdint>

// Haar DWT2D, fused single pass.
// Input:  x  (B=16, C=1, H=2048, W=2048) fp32
// Output: [ll | lh | hl | hh], each (16,1,1024,1024) fp32, concatenated.
//
// Per output pixel (i,j):
//   a = x[2i,2j], b = x[2i,2j+1], c = x[2i+1,2j], d = x[2i+1,2j+1]
//   ll = 0.5(a+b+c+d); lh = 0.5(-a+b-c+d); hl = 0.5(-a-b+c+d); hh = 0.5(a-b-c+d)
//
// Each thread handles 2 adjacent output columns: two float4 input loads,
// four float2 output stores. Fully coalesced both directions.

#define B_  16
#define H_  2048
#define W_  2048
#define HO  (H_/2)     // 1024
#define WO  (W_/2)     // 1024
#define PAIRS_PER_ROW (WO/2)  // 512 threads'-worth per output row

__device__ __forceinline__ float safef(float v) {
    return isfinite(v) ? v : 0.0f;
}

__global__ __launch_bounds__(256)
void dwt2d_haar_kernel(const float* __restrict__ x, float* __restrict__ out) {
    // one thread = one (b, i, j2) where j2 indexes a pair of output columns
    int64_t tid = (int64_t)blockIdx.x * blockDim.x + threadIdx.x;
    const int64_t total = (int64_t)B_ * HO * PAIRS_PER_ROW;
    if (tid >= total) return;

    int j2 = (int)(tid % PAIRS_PER_ROW);          // output col pair index
    int i  = (int)((tid / PAIRS_PER_ROW) % HO);   // output row
    int b  = (int)(tid / ((int64_t)PAIRS_PER_ROW * HO));

    // input offsets: rows 2i and 2i+1, cols 4*j2 .. 4*j2+3
    const int64_t in_base = (int64_t)b * H_ * W_ + (int64_t)(2 * i) * W_ + 4 * j2;
    float4 r0 = *reinterpret_cast<const float4*>(x + in_base);
    float4 r1 = *reinterpret_cast<const float4*>(x + in_base + W_);

    // sanitize inputs (reference _safe)
    float a0 = safef(r0.x), b0 = safef(r0.y);   // block 0, top row
    float a1 = safef(r0.z), b1 = safef(r0.w);   // block 1, top row
    float c0 = safef(r1.x), d0 = safef(r1.y);   // block 0, bottom row
    float c1 = safef(r1.z), d1 = safef(r1.w);   // block 1, bottom row

    const float h = 0.5f;
    float2 ll, lh, hl, hh;
    ll.x = h * ( a0 + b0 + c0 + d0);  ll.y = h * ( a1 + b1 + c1 + d1);
    lh.x = h * (-a0 + b0 - c0 + d0);  lh.y = h * (-a1 + b1 - c1 + d1);
    hl.x = h * (-a0 - b0 + c0 + d0);  hl.y = h * (-a1 - b1 + c1 + d1);
    hh.x = h * ( a0 - b0 - c0 + d0);  hh.y = h * ( a1 - b1 - c1 + d1);

    // outputs finite given finite inputs; clamp anyway to mirror reference
    ll.x = safef(ll.x); ll.y = safef(ll.y);
    lh.x = safef(lh.x); lh.y = safef(lh.y);
    hl.x = safef(hl.x); hl.y = safef(hl.y);
    hh.x = safef(hh.x); hh.y = safef(hh.y);

    const int64_t plane = (int64_t)B_ * HO * WO;   // 16M elements per subband
    const int64_t o = (int64_t)b * HO * WO + (int64_t)i * WO + 2 * j2;

    *reinterpret_cast<float2*>(out + o)             = ll;
    *reinterpret_cast<float2*>(out + plane + o)     = lh;
    *reinterpret_cast<float2*>(out + 2 * plane + o) = hl;
    *reinterpret_cast<float2*>(out + 3 * plane + o) = hh;
}

extern "C" void kernel_launch(void* const* d_in, const int* in_sizes, int n_in,
                              void* d_out, int out_size) {
    const float* x = (const float*)d_in[0];
    float* out = (float*)d_out;

    const int64_t total = (int64_t)B_ * HO * PAIRS_PER_ROW;  // 8,388,608 threads
    const int threads = 256;
    const int blocks = (int)((total + threads - 1) / threads);
    dwt2d_haar_kernel<<<blocks, threads>>>(x, out);
}